// round 1
// baseline (speedup 1.0000x reference)
#include <cuda_runtime.h>
#include <math.h>

// Problem constants
#define BATCH   32
#define SEQ     512
#define TOK     16384        // BATCH*SEQ
#define CDIM    768
#define C3      2304
#define HID     3072
#define NHEAD   12
#define HD      64           // head dim
#define ATT_SCALE 0.125f     // 1/sqrt(64)

// ---------------------------------------------------------------------------
// Scratch (static device globals; allocation-free per harness rules)
// ---------------------------------------------------------------------------
__device__ float g_h  [(size_t)TOK * CDIM];   // LN output (reused for ln1 & ln2)
__device__ float g_qkv[(size_t)TOK * C3];     // QKV projections
__device__ float g_ao [(size_t)TOK * CDIM];   // attention output (pre-proj)
__device__ float g_x2 [(size_t)TOK * CDIM];   // residual stream x = 2*proj(...)
__device__ float g_fc1[(size_t)TOK * HID];    // FC1+GELU output

// ---------------------------------------------------------------------------
// LayerNorm: one block per token row (C=768), 256 threads, 3 elems/thread
// ---------------------------------------------------------------------------
__global__ __launch_bounds__(256)
void ln_kernel(const float* __restrict__ in, const float* __restrict__ w,
               const float* __restrict__ b, float* __restrict__ out)
{
    __shared__ float red[8];
    const int row = blockIdx.x;
    const int t   = threadIdx.x;
    const float* xr = in + (size_t)row * CDIM;

    float v0 = xr[t], v1 = xr[t + 256], v2 = xr[t + 512];

    // --- mean ---
    float s = v0 + v1 + v2;
    #pragma unroll
    for (int o = 16; o > 0; o >>= 1) s += __shfl_xor_sync(0xffffffffu, s, o);
    if ((t & 31) == 0) red[t >> 5] = s;
    __syncthreads();
    float mean = (red[0]+red[1]+red[2]+red[3]+red[4]+red[5]+red[6]+red[7]) * (1.f/CDIM);
    __syncthreads();

    float d0 = v0 - mean, d1 = v1 - mean, d2 = v2 - mean;

    // --- variance ---
    float q = d0*d0 + d1*d1 + d2*d2;
    #pragma unroll
    for (int o = 16; o > 0; o >>= 1) q += __shfl_xor_sync(0xffffffffu, q, o);
    if ((t & 31) == 0) red[t >> 5] = q;
    __syncthreads();
    float var = (red[0]+red[1]+red[2]+red[3]+red[4]+red[5]+red[6]+red[7]) * (1.f/CDIM);
    float r = rsqrtf(var + 1e-5f);

    float* orow = out + (size_t)row * CDIM;
    orow[t]       = d0 * r * w[t]       + b[t];
    orow[t + 256] = d1 * r * w[t + 256] + b[t + 256];
    orow[t + 512] = d2 * r * w[t + 512] + b[t + 512];
}

// ---------------------------------------------------------------------------
// NT SGEMM: C[M,Nn] = A[M,K] * B[Nn,K]^T (+ epilogue)
// 128x128 block tile, BK=16, 256 threads, 8x8 per-thread tile.
// EPI: 0=none  1=2*(acc+bias)  2=gelu(acc+bias)  3=acc+bias+res
// ---------------------------------------------------------------------------
#define BM 128
#define BN 128
#define BK 16

template<int EPI>
__global__ __launch_bounds__(256)
void gemm_nt(const float* __restrict__ A, const float* __restrict__ B,
             const float* __restrict__ bias, const float* __restrict__ Res,
             float* __restrict__ C, int M, int Nn, int K)
{
    __shared__ float As[BK][BM + 4];
    __shared__ float Bs[BK][BN + 4];

    const int tid = threadIdx.x;
    const int tx = tid & 15, ty = tid >> 4;
    const int n0 = blockIdx.x * BN;
    const int m0 = blockIdx.y * BM;

    const float* Ag = A + (size_t)m0 * K;
    const float* Bg = B + (size_t)n0 * K;

    float acc[8][8];
    #pragma unroll
    for (int i = 0; i < 8; i++)
        #pragma unroll
        for (int j = 0; j < 8; j++) acc[i][j] = 0.f;

    for (int kt = 0; kt < K; kt += BK) {
        #pragma unroll
        for (int i = 0; i < 2; i++) {
            int idx = tid + i * 256;
            int row = idx >> 2, kq = (idx & 3) << 2;
            float4 va = *(const float4*)(Ag + (size_t)row * K + kt + kq);
            As[kq+0][row] = va.x; As[kq+1][row] = va.y;
            As[kq+2][row] = va.z; As[kq+3][row] = va.w;
            float4 vb = *(const float4*)(Bg + (size_t)row * K + kt + kq);
            Bs[kq+0][row] = vb.x; Bs[kq+1][row] = vb.y;
            Bs[kq+2][row] = vb.z; Bs[kq+3][row] = vb.w;
        }
        __syncthreads();

        #pragma unroll
        for (int k = 0; k < BK; k++) {
            float a[8], b[8];
            *(float4*)&a[0] = *(const float4*)&As[k][ty * 8];
            *(float4*)&a[4] = *(const float4*)&As[k][ty * 8 + 4];
            *(float4*)&b[0] = *(const float4*)&Bs[k][tx * 8];
            *(float4*)&b[4] = *(const float4*)&Bs[k][tx * 8 + 4];
            #pragma unroll
            for (int i = 0; i < 8; i++)
                #pragma unroll
                for (int j = 0; j < 8; j++)
                    acc[i][j] += a[i] * b[j];
        }
        __syncthreads();
    }

    // Epilogue
    #pragma unroll
    for (int i = 0; i < 8; i++) {
        size_t gm = (size_t)(m0 + ty * 8 + i);
        float* crow = C + gm * Nn + n0 + tx * 8;
        #pragma unroll
        for (int jv = 0; jv < 2; jv++) {
            int gn = n0 + tx * 8 + jv * 4;
            float4 r;
            r.x = acc[i][jv*4+0]; r.y = acc[i][jv*4+1];
            r.z = acc[i][jv*4+2]; r.w = acc[i][jv*4+3];
            if (EPI >= 1) {
                float4 bb = *(const float4*)(bias + gn);
                r.x += bb.x; r.y += bb.y; r.z += bb.z; r.w += bb.w;
            }
            if (EPI == 1) { r.x *= 2.f; r.y *= 2.f; r.z *= 2.f; r.w *= 2.f; }
            if (EPI == 2) {
                r.x = 0.5f * r.x * (1.f + erff(r.x * 0.70710678118654752f));
                r.y = 0.5f * r.y * (1.f + erff(r.y * 0.70710678118654752f));
                r.z = 0.5f * r.z * (1.f + erff(r.z * 0.70710678118654752f));
                r.w = 0.5f * r.w * (1.f + erff(r.w * 0.70710678118654752f));
            }
            if (EPI == 3) {
                float4 rv = *(const float4*)(Res + gm * Nn + gn);
                r.x += rv.x; r.y += rv.y; r.z += rv.z; r.w += rv.w;
            }
            *(float4*)(crow + jv * 4) = r;
        }
    }
}

// ---------------------------------------------------------------------------
// Fused flash attention (fp32): one block per (b, h, 64-query tile).
// Online softmax over 8 key tiles of 64. smem: Q,K,V,S tiles (64x68 each).
// Reads g_qkv, writes g_ao (pre-projection attention output in [B,N,C]).
// ---------------------------------------------------------------------------
#define APAD 68

__global__ __launch_bounds__(256)
void attn_kernel()
{
    extern __shared__ float sm[];
    float* Qs = sm;
    float* Ks = sm + 64 * APAD;
    float* Vs = sm + 2 * 64 * APAD;
    float* Ss = sm + 3 * 64 * APAD;

    const int qt = blockIdx.x;      // query tile 0..7
    const int h  = blockIdx.y;      // head 0..11
    const int b  = blockIdx.z;      // batch 0..31
    const int tid = threadIdx.x;
    const int tx = tid & 15, ty = tid >> 4;

    // load Q tile [64 x 64]
    #pragma unroll
    for (int i = 0; i < 4; i++) {
        int idx = tid + i * 256;
        int row = idx >> 4, c4 = (idx & 15) << 2;
        size_t off = (size_t)(b * SEQ + qt * 64 + row) * C3 + h * HD + c4;
        *(float4*)&Qs[row * APAD + c4] = *(const float4*)(g_qkv + off);
    }

    float o[4][4];
    float m[4], l[4];
    #pragma unroll
    for (int i = 0; i < 4; i++) {
        m[i] = -1e30f; l[i] = 0.f;
        #pragma unroll
        for (int j = 0; j < 4; j++) o[i][j] = 0.f;
    }

    for (int kt = 0; kt < 8; kt++) {
        __syncthreads();   // protect K/V/S from prior iteration readers
        // load K and V tiles [64 x 64]
        #pragma unroll
        for (int i = 0; i < 4; i++) {
            int idx = tid + i * 256;
            int row = idx >> 4, c4 = (idx & 15) << 2;
            size_t off = (size_t)(b * SEQ + kt * 64 + row) * C3 + h * HD + c4;
            *(float4*)&Ks[row * APAD + c4] = *(const float4*)(g_qkv + off + CDIM);
            *(float4*)&Vs[row * APAD + c4] = *(const float4*)(g_qkv + off + 2 * CDIM);
        }
        __syncthreads();

        // S = Q K^T (4x4 per thread: rows ty*4.., key-cols tx*4..)
        float s[4][4];
        #pragma unroll
        for (int i = 0; i < 4; i++)
            #pragma unroll
            for (int j = 0; j < 4; j++) s[i][j] = 0.f;

        #pragma unroll
        for (int kk = 0; kk < HD; kk += 4) {
            float4 qv[4], kv[4];
            #pragma unroll
            for (int i = 0; i < 4; i++) qv[i] = *(const float4*)&Qs[(ty*4+i)*APAD + kk];
            #pragma unroll
            for (int j = 0; j < 4; j++) kv[j] = *(const float4*)&Ks[(tx*4+j)*APAD + kk];
            #pragma unroll
            for (int i = 0; i < 4; i++)
                #pragma unroll
                for (int j = 0; j < 4; j++)
                    s[i][j] += qv[i].x*kv[j].x + qv[i].y*kv[j].y
                             + qv[i].z*kv[j].z + qv[i].w*kv[j].w;
        }

        // online softmax update per query row (16 tx-threads share a row)
        #pragma unroll
        for (int i = 0; i < 4; i++) {
            float s0 = s[i][0]*ATT_SCALE, s1 = s[i][1]*ATT_SCALE;
            float s2 = s[i][2]*ATT_SCALE, s3 = s[i][3]*ATT_SCALE;
            float mloc = fmaxf(fmaxf(s0, s1), fmaxf(s2, s3));
            #pragma unroll
            for (int off = 8; off >= 1; off >>= 1)
                mloc = fmaxf(mloc, __shfl_xor_sync(0xffffffffu, mloc, off, 16));
            float newm = fmaxf(m[i], mloc);
            float fac  = __expf(m[i] - newm);
            float p0 = __expf(s0 - newm), p1 = __expf(s1 - newm);
            float p2 = __expf(s2 - newm), p3 = __expf(s3 - newm);
            float rs = p0 + p1 + p2 + p3;
            #pragma unroll
            for (int off = 8; off >= 1; off >>= 1)
                rs += __shfl_xor_sync(0xffffffffu, rs, off, 16);
            l[i] = l[i] * fac + rs;
            m[i] = newm;
            o[i][0] *= fac; o[i][1] *= fac; o[i][2] *= fac; o[i][3] *= fac;
            float4 pv; pv.x = p0; pv.y = p1; pv.z = p2; pv.w = p3;
            *(float4*)&Ss[(ty*4+i)*APAD + tx*4] = pv;
        }
        __syncthreads();

        // O += P * V  (d-cols tx*4..)
        #pragma unroll
        for (int kk = 0; kk < 64; kk += 4) {
            float4 p4[4], v4[4];
            #pragma unroll
            for (int i = 0; i < 4; i++) p4[i] = *(const float4*)&Ss[(ty*4+i)*APAD + kk];
            #pragma unroll
            for (int k = 0; k < 4; k++) v4[k] = *(const float4*)&Vs[(kk+k)*APAD + tx*4];
            #pragma unroll
            for (int i = 0; i < 4; i++) {
                o[i][0] += p4[i].x*v4[0].x + p4[i].y*v4[1].x + p4[i].z*v4[2].x + p4[i].w*v4[3].x;
                o[i][1] += p4[i].x*v4[0].y + p4[i].y*v4[1].y + p4[i].z*v4[2].y + p4[i].w*v4[3].y;
                o[i][2] += p4[i].x*v4[0].z + p4[i].y*v4[1].z + p4[i].z*v4[2].z + p4[i].w*v4[3].z;
                o[i][3] += p4[i].x*v4[0].w + p4[i].y*v4[1].w + p4[i].z*v4[2].w + p4[i].w*v4[3].w;
            }
        }
    }

    // finalize + write [B,N,C] layout
    #pragma unroll
    for (int i = 0; i < 4; i++) {
        float inv = 1.f / l[i];
        float4 r;
        r.x = o[i][0]*inv; r.y = o[i][1]*inv; r.z = o[i][2]*inv; r.w = o[i][3]*inv;
        size_t off = (size_t)(b * SEQ + qt * 64 + ty * 4 + i) * CDIM + h * HD + tx * 4;
        *(float4*)(g_ao + off) = r;
    }
}

// ---------------------------------------------------------------------------
// Launch
// ---------------------------------------------------------------------------
extern "C" void kernel_launch(void* const* d_in, const int* in_sizes, int n_in,
                              void* d_out, int out_size)
{
    const float* x      = (const float*)d_in[0];
    const float* ln1_w  = (const float*)d_in[1];
    const float* ln1_b  = (const float*)d_in[2];
    const float* qkv_w  = (const float*)d_in[3];
    const float* proj_w = (const float*)d_in[4];
    const float* proj_b = (const float*)d_in[5];
    const float* ln2_w  = (const float*)d_in[6];
    const float* ln2_b  = (const float*)d_in[7];
    const float* fc1_w  = (const float*)d_in[8];
    const float* fc1_b  = (const float*)d_in[9];
    const float* fc2_w  = (const float*)d_in[10];
    const float* fc2_b  = (const float*)d_in[11];
    float* out = (float*)d_out;

    float *ph, *pqkv, *pao, *px2, *pfc1;
    cudaGetSymbolAddress((void**)&ph,   g_h);
    cudaGetSymbolAddress((void**)&pqkv, g_qkv);
    cudaGetSymbolAddress((void**)&pao,  g_ao);
    cudaGetSymbolAddress((void**)&px2,  g_x2);
    cudaGetSymbolAddress((void**)&pfc1, g_fc1);

    const int attn_smem = 4 * 64 * APAD * sizeof(float);   // ~69.6 KB
    cudaFuncSetAttribute(attn_kernel,
                         cudaFuncAttributeMaxDynamicSharedMemorySize, attn_smem);

    // 1) LN1
    ln_kernel<<<TOK, 256>>>(x, ln1_w, ln1_b, ph);

    // 2) QKV = LN1(x) @ qkv_w^T            [16384 x 2304 x 768]
    gemm_nt<0><<<dim3(C3 / BN, TOK / BM), 256>>>(ph, qkv_w, nullptr, nullptr,
                                                 pqkv, TOK, C3, CDIM);

    // 3) fused multi-head attention -> g_ao
    attn_kernel<<<dim3(SEQ / 64, NHEAD, BATCH), 256, attn_smem>>>();

    // 4) x = 2*(attn @ proj_w^T + proj_b)  [16384 x 768 x 768]
    gemm_nt<1><<<dim3(CDIM / BN, TOK / BM), 256>>>(pao, proj_w, proj_b, nullptr,
                                                   px2, TOK, CDIM, CDIM);

    // 5) LN2
    ln_kernel<<<TOK, 256>>>(px2, ln2_w, ln2_b, ph);

    // 6) FC1 + GELU                        [16384 x 3072 x 768]
    gemm_nt<2><<<dim3(HID / BN, TOK / BM), 256>>>(ph, fc1_w, fc1_b, nullptr,
                                                  pfc1, TOK, HID, CDIM);

    // 7) out = FC1g @ fc2_w^T + fc2_b + x  [16384 x 768 x 3072]
    gemm_nt<3><<<dim3(CDIM / BN, TOK / BM), 256>>>(pfc1, fc2_w, fc2_b, px2,
                                                   out, TOK, CDIM, HID);
}

// round 3
// speedup vs baseline: 3.3730x; 3.3730x over previous
#include <cuda_runtime.h>
#include <cuda_fp16.h>
#include <math.h>
#include <stdint.h>

// ---------------------------------------------------------------------------
// Problem constants
// ---------------------------------------------------------------------------
#define BATCH   32
#define SEQ     512
#define TOK     16384
#define CDIM    768
#define C3      2304
#define HID     3072
#define NHEAD   12
#define HD      64
#define ATT_SCALE 0.125f

// ---------------------------------------------------------------------------
// Scratch buffers
// ---------------------------------------------------------------------------
__device__ __half g_hH  [(size_t)TOK * CDIM];    // LN out (fp16)
__device__ __half g_aoH [(size_t)TOK * CDIM];    // attention out (fp16)
__device__ __half g_fc1H[(size_t)TOK * HID];     // FC1+GELU out (fp16)
__device__ float  g_qkv [(size_t)TOK * C3];      // QKV (fp32, attention input)
__device__ float  g_x2  [(size_t)TOK * CDIM];    // residual stream
__device__ __half g_qkvw [(size_t)C3  * CDIM];   // fp16 weights
__device__ __half g_projw[(size_t)CDIM * CDIM];
__device__ __half g_fc1w [(size_t)HID * CDIM];
__device__ __half g_fc2w [(size_t)CDIM * HID];

// ---------------------------------------------------------------------------
// Helpers
// ---------------------------------------------------------------------------
__device__ __forceinline__ uint32_t smem_u32(const void* p) {
    uint32_t a;
    asm("{ .reg .u64 t; cvta.to.shared.u64 t, %1; cvt.u32.u64 %0, t; }" : "=r"(a) : "l"(p));
    return a;
}
__device__ __forceinline__ void cpa16(uint32_t s, const void* g) {
    asm volatile("cp.async.cg.shared.global [%0], [%1], 16;\n" :: "r"(s), "l"(g) : "memory");
}
#define CP_COMMIT() asm volatile("cp.async.commit_group;\n" ::: "memory")
#define CP_WAIT2()  asm volatile("cp.async.wait_group 2;\n" ::: "memory")
#define CP_WAIT0()  asm volatile("cp.async.wait_group 0;\n" ::: "memory")

__device__ __forceinline__ void ldmx4(uint32_t* r, uint32_t addr) {
    asm volatile("ldmatrix.sync.aligned.m8n8.x4.shared.b16 {%0,%1,%2,%3}, [%4];"
                 : "=r"(r[0]), "=r"(r[1]), "=r"(r[2]), "=r"(r[3]) : "r"(addr));
}
__device__ __forceinline__ void mma16816(float* d, const uint32_t* a, const uint32_t* b) {
    asm volatile(
        "mma.sync.aligned.m16n8k16.row.col.f32.f16.f16.f32 "
        "{%0,%1,%2,%3}, {%4,%5,%6,%7}, {%8,%9}, {%0,%1,%2,%3};"
        : "+f"(d[0]), "+f"(d[1]), "+f"(d[2]), "+f"(d[3])
        : "r"(a[0]), "r"(a[1]), "r"(a[2]), "r"(a[3]), "r"(b[0]), "r"(b[1]));
}

// smem tile: 128 rows x 32 fp16 (64B/row = 4 x 16B chunks), XOR swizzle.
// chunk' = chunk ^ ((row>>1)&3): all 8 16B-accesses of an ldmatrix phase land
// in distinct bank groups.
__device__ __forceinline__ uint32_t swz(int row, int chunk) {
    return (uint32_t)(row * 64 + ((chunk ^ ((row >> 1) & 3)) << 4));
}

// ---------------------------------------------------------------------------
// HMMA GEMM: C[M,Nn] = A[M,K] * B[Nn,K]^T  (fp16 in, fp32 accum)
// 128x128x32 tile, 8 warps (warp tile 64x32), 4-stage cp.async pipeline.
// EPI: 0 fp32 | 1 fp32 2*(v+bias) | 2 fp16 gelu(v+bias) | 3 fp32 v+bias+res
// ---------------------------------------------------------------------------
#define BM 128
#define BN 128
#define BK 32
#define GSTAGES 4
#define ST_A    8192              // 128*32*2
#define ST_BYTES 16384            // A + B per stage
#define GEMM_SMEM (GSTAGES * ST_BYTES)

__device__ __forceinline__ void load_stage(
    const __half* A, const __half* B, int m0, int n0, int K, int kt,
    uint32_t sA, uint32_t sB, int tid)
{
    #pragma unroll
    for (int j = 0; j < 2; j++) {
        int cid = tid + j * 256;
        int row = cid >> 2, c = cid & 3;
        cpa16(sA + swz(row, c), A + (size_t)(m0 + row) * K + kt + c * 8);
    }
    #pragma unroll
    for (int j = 0; j < 2; j++) {
        int cid = tid + j * 256;
        int row = cid >> 2, c = cid & 3;
        cpa16(sB + swz(row, c), B + (size_t)(n0 + row) * K + kt + c * 8);
    }
}

template<int EPI>
__global__ void __launch_bounds__(256, 2)
gemm_hmma(const __half* __restrict__ A, const __half* __restrict__ B,
          const float* __restrict__ bias, const float* __restrict__ Res,
          float* __restrict__ Co, __half* __restrict__ CoH, int Nn, int K)
{
    extern __shared__ __align__(1024) char smem[];
    const uint32_t sb = smem_u32(smem);
    const int tid  = threadIdx.x;
    const int lane = tid & 31;
    const int wid  = tid >> 5;
    const int wm   = (wid >> 2) * 64;
    const int wn   = (wid & 3) * 32;
    const int m0   = blockIdx.y * BM;
    const int n0   = blockIdx.x * BN;

    // per-lane ldmatrix row/chunk offsets
    const int raA = (lane & 7) + ((lane >> 3) & 1) * 8;
    const int caA = lane >> 4;
    const int raB = (lane & 7) + ((lane >> 4) & 1) * 8;
    const int caB = (lane >> 3) & 1;

    float acc[4][4][4];
    #pragma unroll
    for (int i = 0; i < 4; i++)
        #pragma unroll
        for (int j = 0; j < 4; j++)
            #pragma unroll
            for (int q = 0; q < 4; q++) acc[i][j][q] = 0.f;

    const int nc = K / BK;

    #pragma unroll
    for (int c = 0; c < GSTAGES - 1; c++) {
        load_stage(A, B, m0, n0, K, c * BK, sb + c * ST_BYTES, sb + c * ST_BYTES + ST_A, tid);
        CP_COMMIT();
    }

    for (int c = 0; c < nc; c++) {
        CP_WAIT2();
        __syncthreads();
        if (c + GSTAGES - 1 < nc) {
            const int s = (c + GSTAGES - 1) & (GSTAGES - 1);
            load_stage(A, B, m0, n0, K, (c + GSTAGES - 1) * BK,
                       sb + s * ST_BYTES, sb + s * ST_BYTES + ST_A, tid);
        }
        CP_COMMIT();

        const uint32_t sA = sb + (c & (GSTAGES - 1)) * ST_BYTES;
        const uint32_t sB = sA + ST_A;
        #pragma unroll
        for (int ks = 0; ks < 2; ks++) {
            const int cb = ks * 2;
            uint32_t a[4][4], b[4][2];
            #pragma unroll
            for (int mi = 0; mi < 4; mi++)
                ldmx4(a[mi], sA + swz(wm + mi * 16 + raA, cb + caA));
            #pragma unroll
            for (int nj = 0; nj < 2; nj++) {
                uint32_t r[4];
                ldmx4(r, sB + swz(wn + nj * 16 + raB, cb + caB));
                b[nj*2][0]   = r[0]; b[nj*2][1]   = r[1];
                b[nj*2+1][0] = r[2]; b[nj*2+1][1] = r[3];
            }
            #pragma unroll
            for (int mi = 0; mi < 4; mi++)
                #pragma unroll
                for (int ni = 0; ni < 4; ni++)
                    mma16816(acc[mi][ni], a[mi], b[ni]);
        }
    }

    // ---- epilogue ----
    const int r0 = lane >> 2;
    const int cp = (lane & 3) * 2;
    #pragma unroll
    for (int mi = 0; mi < 4; mi++) {
        #pragma unroll
        for (int ni = 0; ni < 4; ni++) {
            const int gm = m0 + wm + mi * 16 + r0;
            const int gn = n0 + wn + ni * 8 + cp;
            #pragma unroll
            for (int hr = 0; hr < 2; hr++) {
                const int row = gm + hr * 8;
                float v0 = acc[mi][ni][hr*2+0];
                float v1 = acc[mi][ni][hr*2+1];
                if (EPI >= 1) { v0 += bias[gn]; v1 += bias[gn + 1]; }
                if (EPI == 1) { v0 *= 2.f; v1 *= 2.f; }
                if (EPI == 2) {
                    v0 = 0.5f * v0 * (1.f + erff(v0 * 0.70710678118654752f));
                    v1 = 0.5f * v1 * (1.f + erff(v1 * 0.70710678118654752f));
                    *(__half2*)(CoH + (size_t)row * Nn + gn) =
                        __floats2half2_rn(v0, v1);
                    continue;
                }
                if (EPI == 3) {
                    const float2 rv = *(const float2*)(Res + (size_t)row * Nn + gn);
                    v0 += rv.x; v1 += rv.y;
                }
                float2 o; o.x = v0; o.y = v1;
                *(float2*)(Co + (size_t)row * Nn + gn) = o;
            }
        }
    }
}

// ---------------------------------------------------------------------------
// Weight conversion fp32 -> fp16
// ---------------------------------------------------------------------------
__global__ void wconv(const float* __restrict__ src, __half* __restrict__ dst, int total)
{
    int idx = blockIdx.x * blockDim.x + threadIdx.x;
    if (idx < total) dst[idx] = __float2half(src[idx]);
}

// ---------------------------------------------------------------------------
// LayerNorm -> fp16
// ---------------------------------------------------------------------------
__global__ __launch_bounds__(256)
void ln_kernel(const float* __restrict__ in, const float* __restrict__ w,
               const float* __restrict__ b, __half* __restrict__ out)
{
    __shared__ float red[8];
    const int row = blockIdx.x;
    const int t   = threadIdx.x;
    const float* xr = in + (size_t)row * CDIM;

    float v0 = xr[t], v1 = xr[t + 256], v2 = xr[t + 512];
    float s = v0 + v1 + v2;
    #pragma unroll
    for (int o = 16; o > 0; o >>= 1) s += __shfl_xor_sync(0xffffffffu, s, o);
    if ((t & 31) == 0) red[t >> 5] = s;
    __syncthreads();
    float mean = (red[0]+red[1]+red[2]+red[3]+red[4]+red[5]+red[6]+red[7]) * (1.f/CDIM);
    __syncthreads();
    float d0 = v0 - mean, d1 = v1 - mean, d2 = v2 - mean;
    float q = d0*d0 + d1*d1 + d2*d2;
    #pragma unroll
    for (int o = 16; o > 0; o >>= 1) q += __shfl_xor_sync(0xffffffffu, q, o);
    if ((t & 31) == 0) red[t >> 5] = q;
    __syncthreads();
    float var = (red[0]+red[1]+red[2]+red[3]+red[4]+red[5]+red[6]+red[7]) * (1.f/CDIM);
    float r = rsqrtf(var + 1e-5f);

    __half* orow = out + (size_t)row * CDIM;
    orow[t]       = __float2half(d0 * r * w[t]       + b[t]);
    orow[t + 256] = __float2half(d1 * r * w[t + 256] + b[t + 256]);
    orow[t + 512] = __float2half(d2 * r * w[t + 512] + b[t + 512]);
}

// ---------------------------------------------------------------------------
// Fused flash attention (fp32) -> fp16 output
// ---------------------------------------------------------------------------
#define APAD 68

__global__ __launch_bounds__(256)
void attn_kernel()
{
    extern __shared__ float sm[];
    float* Qs = sm;
    float* Ks = sm + 64 * APAD;
    float* Vs = sm + 2 * 64 * APAD;
    float* Ss = sm + 3 * 64 * APAD;

    const int qt = blockIdx.x;
    const int hh = blockIdx.y;
    const int b  = blockIdx.z;
    const int tid = threadIdx.x;
    const int tx = tid & 15, ty = tid >> 4;

    #pragma unroll
    for (int i = 0; i < 4; i++) {
        int idx = tid + i * 256;
        int row = idx >> 4, c4 = (idx & 15) << 2;
        size_t off = (size_t)(b * SEQ + qt * 64 + row) * C3 + hh * HD + c4;
        *(float4*)&Qs[row * APAD + c4] = *(const float4*)(g_qkv + off);
    }

    float o[4][4], m[4], l[4];
    #pragma unroll
    for (int i = 0; i < 4; i++) {
        m[i] = -1e30f; l[i] = 0.f;
        #pragma unroll
        for (int j = 0; j < 4; j++) o[i][j] = 0.f;
    }

    for (int kt = 0; kt < 8; kt++) {
        __syncthreads();
        #pragma unroll
        for (int i = 0; i < 4; i++) {
            int idx = tid + i * 256;
            int row = idx >> 4, c4 = (idx & 15) << 2;
            size_t off = (size_t)(b * SEQ + kt * 64 + row) * C3 + hh * HD + c4;
            *(float4*)&Ks[row * APAD + c4] = *(const float4*)(g_qkv + off + CDIM);
            *(float4*)&Vs[row * APAD + c4] = *(const float4*)(g_qkv + off + 2 * CDIM);
        }
        __syncthreads();

        float s[4][4];
        #pragma unroll
        for (int i = 0; i < 4; i++)
            #pragma unroll
            for (int j = 0; j < 4; j++) s[i][j] = 0.f;

        #pragma unroll
        for (int kk = 0; kk < HD; kk += 4) {
            float4 qv[4], kv[4];
            #pragma unroll
            for (int i = 0; i < 4; i++) qv[i] = *(const float4*)&Qs[(ty*4+i)*APAD + kk];
            #pragma unroll
            for (int j = 0; j < 4; j++) kv[j] = *(const float4*)&Ks[(tx*4+j)*APAD + kk];
            #pragma unroll
            for (int i = 0; i < 4; i++)
                #pragma unroll
                for (int j = 0; j < 4; j++)
                    s[i][j] += qv[i].x*kv[j].x + qv[i].y*kv[j].y
                             + qv[i].z*kv[j].z + qv[i].w*kv[j].w;
        }

        #pragma unroll
        for (int i = 0; i < 4; i++) {
            float s0 = s[i][0]*ATT_SCALE, s1 = s[i][1]*ATT_SCALE;
            float s2 = s[i][2]*ATT_SCALE, s3 = s[i][3]*ATT_SCALE;
            float mloc = fmaxf(fmaxf(s0, s1), fmaxf(s2, s3));
            #pragma unroll
            for (int off = 8; off >= 1; off >>= 1)
                mloc = fmaxf(mloc, __shfl_xor_sync(0xffffffffu, mloc, off, 16));
            float newm = fmaxf(m[i], mloc);
            float fac  = __expf(m[i] - newm);
            float p0 = __expf(s0 - newm), p1 = __expf(s1 - newm);
            float p2 = __expf(s2 - newm), p3 = __expf(s3 - newm);
            float rs = p0 + p1 + p2 + p3;
            #pragma unroll
            for (int off = 8; off >= 1; off >>= 1)
                rs += __shfl_xor_sync(0xffffffffu, rs, off, 16);
            l[i] = l[i] * fac + rs;
            m[i] = newm;
            o[i][0] *= fac; o[i][1] *= fac; o[i][2] *= fac; o[i][3] *= fac;
            float4 pv; pv.x = p0; pv.y = p1; pv.z = p2; pv.w = p3;
            *(float4*)&Ss[(ty*4+i)*APAD + tx*4] = pv;
        }
        __syncthreads();

        #pragma unroll
        for (int kk = 0; kk < 64; kk += 4) {
            float4 p4[4], v4[4];
            #pragma unroll
            for (int i = 0; i < 4; i++) p4[i] = *(const float4*)&Ss[(ty*4+i)*APAD + kk];
            #pragma unroll
            for (int k = 0; k < 4; k++) v4[k] = *(const float4*)&Vs[(kk+k)*APAD + tx*4];
            #pragma unroll
            for (int i = 0; i < 4; i++) {
                o[i][0] += p4[i].x*v4[0].x + p4[i].y*v4[1].x + p4[i].z*v4[2].x + p4[i].w*v4[3].x;
                o[i][1] += p4[i].x*v4[0].y + p4[i].y*v4[1].y + p4[i].z*v4[2].y + p4[i].w*v4[3].y;
                o[i][2] += p4[i].x*v4[0].z + p4[i].y*v4[1].z + p4[i].z*v4[2].z + p4[i].w*v4[3].z;
                o[i][3] += p4[i].x*v4[0].w + p4[i].y*v4[1].w + p4[i].z*v4[2].w + p4[i].w*v4[3].w;
            }
        }
    }

    #pragma unroll
    for (int i = 0; i < 4; i++) {
        float inv = 1.f / l[i];
        int token = b * SEQ + qt * 64 + ty * 4 + i;
        __half* dst = g_aoH + (size_t)token * CDIM + hh * HD + tx * 4;
        *(__half2*)(dst)     = __floats2half2_rn(o[i][0]*inv, o[i][1]*inv);
        *(__half2*)(dst + 2) = __floats2half2_rn(o[i][2]*inv, o[i][3]*inv);
    }
}

// ---------------------------------------------------------------------------
// Launch
// ---------------------------------------------------------------------------
extern "C" void kernel_launch(void* const* d_in, const int* in_sizes, int n_in,
                              void* d_out, int out_size)
{
    const float* x      = (const float*)d_in[0];
    const float* ln1_w  = (const float*)d_in[1];
    const float* ln1_b  = (const float*)d_in[2];
    const float* qkv_w  = (const float*)d_in[3];
    const float* proj_w = (const float*)d_in[4];
    const float* proj_b = (const float*)d_in[5];
    const float* ln2_w  = (const float*)d_in[6];
    const float* ln2_b  = (const float*)d_in[7];
    const float* fc1_w  = (const float*)d_in[8];
    const float* fc1_b  = (const float*)d_in[9];
    const float* fc2_w  = (const float*)d_in[10];
    const float* fc2_b  = (const float*)d_in[11];
    float* out = (float*)d_out;

    __half *phH, *paoH, *pfc1H, *pqkvw, *pprojw, *pfc1w, *pfc2w;
    float *pqkv, *px2;
    cudaGetSymbolAddress((void**)&phH,   g_hH);
    cudaGetSymbolAddress((void**)&paoH,  g_aoH);
    cudaGetSymbolAddress((void**)&pfc1H, g_fc1H);
    cudaGetSymbolAddress((void**)&pqkv,  g_qkv);
    cudaGetSymbolAddress((void**)&px2,   g_x2);
    cudaGetSymbolAddress((void**)&pqkvw, g_qkvw);
    cudaGetSymbolAddress((void**)&pprojw,g_projw);
    cudaGetSymbolAddress((void**)&pfc1w, g_fc1w);
    cudaGetSymbolAddress((void**)&pfc2w, g_fc2w);

    cudaFuncSetAttribute(gemm_hmma<0>, cudaFuncAttributeMaxDynamicSharedMemorySize, GEMM_SMEM);
    cudaFuncSetAttribute(gemm_hmma<1>, cudaFuncAttributeMaxDynamicSharedMemorySize, GEMM_SMEM);
    cudaFuncSetAttribute(gemm_hmma<2>, cudaFuncAttributeMaxDynamicSharedMemorySize, GEMM_SMEM);
    cudaFuncSetAttribute(gemm_hmma<3>, cudaFuncAttributeMaxDynamicSharedMemorySize, GEMM_SMEM);
    const int attn_smem = 4 * 64 * APAD * sizeof(float);
    cudaFuncSetAttribute(attn_kernel, cudaFuncAttributeMaxDynamicSharedMemorySize, attn_smem);

    // weight conversions (deterministic, every call)
    wconv<<<(C3 * CDIM + 255) / 256, 256>>>(qkv_w,  pqkvw,  C3 * CDIM);
    wconv<<<(CDIM * CDIM + 255) / 256, 256>>>(proj_w, pprojw, CDIM * CDIM);
    wconv<<<(HID * CDIM + 255) / 256, 256>>>(fc1_w,  pfc1w,  HID * CDIM);
    wconv<<<(CDIM * HID + 255) / 256, 256>>>(fc2_w,  pfc2w,  CDIM * HID);

    // 1) LN1 -> fp16
    ln_kernel<<<TOK, 256>>>(x, ln1_w, ln1_b, phH);

    // 2) QKV [16384 x 2304 x 768] -> fp32 g_qkv
    gemm_hmma<0><<<dim3(C3 / BN, TOK / BM), 256, GEMM_SMEM>>>(
        phH, pqkvw, nullptr, nullptr, pqkv, nullptr, C3, CDIM);

    // 3) attention -> fp16 g_aoH
    attn_kernel<<<dim3(SEQ / 64, NHEAD, BATCH), 256, attn_smem>>>();

    // 4) x = 2*(attn @ proj_w^T + proj_b) -> fp32 g_x2
    gemm_hmma<1><<<dim3(CDIM / BN, TOK / BM), 256, GEMM_SMEM>>>(
        paoH, pprojw, proj_b, nullptr, px2, nullptr, CDIM, CDIM);

    // 5) LN2 -> fp16
    ln_kernel<<<TOK, 256>>>(px2, ln2_w, ln2_b, phH);

    // 6) FC1 + GELU -> fp16 g_fc1H  [16384 x 3072 x 768]
    gemm_hmma<2><<<dim3(HID / BN, TOK / BM), 256, GEMM_SMEM>>>(
        phH, pfc1w, fc1_b, nullptr, nullptr, pfc1H, HID, CDIM);

    // 7) out = fc1g @ fc2_w^T + fc2_b + x  [16384 x 768 x 3072]
    gemm_hmma<3><<<dim3(CDIM / BN, TOK / BM), 256, GEMM_SMEM>>>(
        pfc1H, pfc2w, fc2_b, px2, out, nullptr, CDIM, HID);
}

// round 4
// speedup vs baseline: 7.3015x; 2.1647x over previous
#include <cuda_runtime.h>
#include <cuda_fp16.h>
#include <math.h>
#include <stdint.h>

// ---------------------------------------------------------------------------
// Problem constants
// ---------------------------------------------------------------------------
#define BATCH   32
#define SEQ     512
#define TOK     16384
#define CDIM    768
#define C3      2304
#define HID     3072
#define NHEAD   12
#define HD      64
#define SCL2E   0.180336880f   // 0.125 * log2(e)

// ---------------------------------------------------------------------------
// Scratch buffers
// ---------------------------------------------------------------------------
__device__ __half g_hH  [(size_t)TOK * CDIM];    // LN out (fp16)
__device__ __half g_aoH [(size_t)TOK * CDIM];    // attention out (fp16)
__device__ __half g_fc1H[(size_t)TOK * HID];     // FC1+GELU out (fp16)
__device__ __half g_qkvH[(size_t)TOK * C3];      // QKV (fp16)
__device__ float  g_x2  [(size_t)TOK * CDIM];    // residual stream (fp32)
__device__ __half g_qkvw [(size_t)C3  * CDIM];   // fp16 weights
__device__ __half g_projw[(size_t)CDIM * CDIM];
__device__ __half g_fc1w [(size_t)HID * CDIM];
__device__ __half g_fc2w [(size_t)CDIM * HID];

// ---------------------------------------------------------------------------
// Helpers
// ---------------------------------------------------------------------------
__device__ __forceinline__ uint32_t smem_u32(const void* p) {
    uint32_t a;
    asm("{ .reg .u64 t; cvta.to.shared.u64 t, %1; cvt.u32.u64 %0, t; }" : "=r"(a) : "l"(p));
    return a;
}
__device__ __forceinline__ void cpa16(uint32_t s, const void* g) {
    asm volatile("cp.async.cg.shared.global [%0], [%1], 16;\n" :: "r"(s), "l"(g) : "memory");
}
#define CP_COMMIT() asm volatile("cp.async.commit_group;\n" ::: "memory")
#define CP_WAIT2()  asm volatile("cp.async.wait_group 2;\n" ::: "memory")
#define CP_WAIT0()  asm volatile("cp.async.wait_group 0;\n" ::: "memory")

__device__ __forceinline__ void ldmx4(uint32_t* r, uint32_t addr) {
    asm volatile("ldmatrix.sync.aligned.m8n8.x4.shared.b16 {%0,%1,%2,%3}, [%4];"
                 : "=r"(r[0]), "=r"(r[1]), "=r"(r[2]), "=r"(r[3]) : "r"(addr));
}
__device__ __forceinline__ void ldmx4t(uint32_t* r, uint32_t addr) {
    asm volatile("ldmatrix.sync.aligned.m8n8.x4.trans.shared.b16 {%0,%1,%2,%3}, [%4];"
                 : "=r"(r[0]), "=r"(r[1]), "=r"(r[2]), "=r"(r[3]) : "r"(addr));
}
__device__ __forceinline__ void mma16816(float* d, const uint32_t* a, const uint32_t* b) {
    asm volatile(
        "mma.sync.aligned.m16n8k16.row.col.f32.f16.f16.f32 "
        "{%0,%1,%2,%3}, {%4,%5,%6,%7}, {%8,%9}, {%0,%1,%2,%3};"
        : "+f"(d[0]), "+f"(d[1]), "+f"(d[2]), "+f"(d[3])
        : "r"(a[0]), "r"(a[1]), "r"(a[2]), "r"(a[3]), "r"(b[0]), "r"(b[1]));
}
__device__ __forceinline__ uint32_t h2u(float a, float b) {
    __half2 h = __floats2half2_rn(a, b);
    return *(uint32_t*)&h;
}

// exp2 on the FMA pipe (deg-5 Taylor, rel err ~2e-6); arg clamped to [-80, 0+]
__device__ __forceinline__ float exp2p(float x) {
    x = fmaxf(x, -80.f);
    float kf = rintf(x);
    float f  = x - kf;
    float p  = 1.33333575e-3f;
    p = fmaf(p, f, 9.61812076e-3f);
    p = fmaf(p, f, 5.55041086e-2f);
    p = fmaf(p, f, 2.40226507e-1f);
    p = fmaf(p, f, 6.93147181e-1f);
    p = fmaf(p, f, 1.0f);
    return __int_as_float(((int)kf + 127) << 23) * p;
}

// GEMM smem swizzle: 64B rows (4 chunks)
__device__ __forceinline__ uint32_t swz(int row, int chunk) {
    return (uint32_t)(row * 64 + ((chunk ^ ((row >> 1) & 3)) << 4));
}
// Attention smem swizzle: 128B rows (8 chunks)
__device__ __forceinline__ uint32_t swz8(int row, int chunk) {
    return (uint32_t)(row * 128 + ((chunk ^ (row & 7)) << 4));
}

// ---------------------------------------------------------------------------
// HMMA GEMM: C[M,Nn] = A[M,K] * B[Nn,K]^T  (fp16 in, fp32 accum)
// EPI: 0 fp32 | 1 fp32 2*(v+bias) | 2 fp16 gelu(v+bias) | 3 fp32 v+bias+res
//      4 fp16 plain
// ---------------------------------------------------------------------------
#define BM 128
#define BN 128
#define BK 32
#define GSTAGES 4
#define ST_A    8192
#define ST_BYTES 16384
#define GEMM_SMEM (GSTAGES * ST_BYTES)

__device__ __forceinline__ void load_stage(
    const __half* A, const __half* B, int m0, int n0, int K, int kt,
    uint32_t sA, uint32_t sB, int tid)
{
    #pragma unroll
    for (int j = 0; j < 2; j++) {
        int cid = tid + j * 256;
        int row = cid >> 2, c = cid & 3;
        cpa16(sA + swz(row, c), A + (size_t)(m0 + row) * K + kt + c * 8);
    }
    #pragma unroll
    for (int j = 0; j < 2; j++) {
        int cid = tid + j * 256;
        int row = cid >> 2, c = cid & 3;
        cpa16(sB + swz(row, c), B + (size_t)(n0 + row) * K + kt + c * 8);
    }
}

template<int EPI>
__global__ void __launch_bounds__(256, 2)
gemm_hmma(const __half* __restrict__ A, const __half* __restrict__ B,
          const float* __restrict__ bias, const float* __restrict__ Res,
          float* __restrict__ Co, __half* __restrict__ CoH, int Nn, int K)
{
    extern __shared__ __align__(1024) char smem[];
    const uint32_t sb = smem_u32(smem);
    const int tid  = threadIdx.x;
    const int lane = tid & 31;
    const int wid  = tid >> 5;
    const int wm   = (wid >> 2) * 64;
    const int wn   = (wid & 3) * 32;
    const int m0   = blockIdx.y * BM;
    const int n0   = blockIdx.x * BN;

    const int raA = (lane & 15);
    const int caA = lane >> 4;
    const int raB = (lane & 7) + ((lane >> 4) & 1) * 8;
    const int caB = (lane >> 3) & 1;

    float acc[4][4][4];
    #pragma unroll
    for (int i = 0; i < 4; i++)
        #pragma unroll
        for (int j = 0; j < 4; j++)
            #pragma unroll
            for (int q = 0; q < 4; q++) acc[i][j][q] = 0.f;

    const int nc = K / BK;

    #pragma unroll
    for (int c = 0; c < GSTAGES - 1; c++) {
        load_stage(A, B, m0, n0, K, c * BK, sb + c * ST_BYTES, sb + c * ST_BYTES + ST_A, tid);
        CP_COMMIT();
    }

    for (int c = 0; c < nc; c++) {
        CP_WAIT2();
        __syncthreads();
        if (c + GSTAGES - 1 < nc) {
            const int s = (c + GSTAGES - 1) & (GSTAGES - 1);
            load_stage(A, B, m0, n0, K, (c + GSTAGES - 1) * BK,
                       sb + s * ST_BYTES, sb + s * ST_BYTES + ST_A, tid);
        }
        CP_COMMIT();

        const uint32_t sA = sb + (c & (GSTAGES - 1)) * ST_BYTES;
        const uint32_t sB = sA + ST_A;
        #pragma unroll
        for (int ks = 0; ks < 2; ks++) {
            const int cb = ks * 2;
            uint32_t a[4][4], b[4][2];
            #pragma unroll
            for (int mi = 0; mi < 4; mi++)
                ldmx4(a[mi], sA + swz(wm + mi * 16 + raA, cb + caA));
            #pragma unroll
            for (int nj = 0; nj < 2; nj++) {
                uint32_t r[4];
                ldmx4(r, sB + swz(wn + nj * 16 + raB, cb + caB));
                b[nj*2][0]   = r[0]; b[nj*2][1]   = r[1];
                b[nj*2+1][0] = r[2]; b[nj*2+1][1] = r[3];
            }
            #pragma unroll
            for (int mi = 0; mi < 4; mi++)
                #pragma unroll
                for (int ni = 0; ni < 4; ni++)
                    mma16816(acc[mi][ni], a[mi], b[ni]);
        }
    }

    // ---- epilogue ----
    const int r0 = lane >> 2;
    const int cp = (lane & 3) * 2;
    #pragma unroll
    for (int mi = 0; mi < 4; mi++) {
        #pragma unroll
        for (int ni = 0; ni < 4; ni++) {
            const int gm = m0 + wm + mi * 16 + r0;
            const int gn = n0 + wn + ni * 8 + cp;
            #pragma unroll
            for (int hr = 0; hr < 2; hr++) {
                const int row = gm + hr * 8;
                float v0 = acc[mi][ni][hr*2+0];
                float v1 = acc[mi][ni][hr*2+1];
                if (EPI == 4) {
                    *(__half2*)(CoH + (size_t)row * Nn + gn) = __floats2half2_rn(v0, v1);
                    continue;
                }
                if (EPI >= 1) { v0 += bias[gn]; v1 += bias[gn + 1]; }
                if (EPI == 1) { v0 *= 2.f; v1 *= 2.f; }
                if (EPI == 2) {
                    v0 = 0.5f * v0 * (1.f + erff(v0 * 0.70710678118654752f));
                    v1 = 0.5f * v1 * (1.f + erff(v1 * 0.70710678118654752f));
                    *(__half2*)(CoH + (size_t)row * Nn + gn) = __floats2half2_rn(v0, v1);
                    continue;
                }
                if (EPI == 3) {
                    const float2 rv = *(const float2*)(Res + (size_t)row * Nn + gn);
                    v0 += rv.x; v1 += rv.y;
                }
                float2 o; o.x = v0; o.y = v1;
                *(float2*)(Co + (size_t)row * Nn + gn) = o;
            }
        }
    }
}

// ---------------------------------------------------------------------------
// Weight conversion fp32 -> fp16
// ---------------------------------------------------------------------------
__global__ void wconv(const float* __restrict__ src, __half* __restrict__ dst, int total)
{
    int idx = blockIdx.x * blockDim.x + threadIdx.x;
    if (idx < total) dst[idx] = __float2half(src[idx]);
}

// ---------------------------------------------------------------------------
// LayerNorm -> fp16
// ---------------------------------------------------------------------------
__global__ __launch_bounds__(256)
void ln_kernel(const float* __restrict__ in, const float* __restrict__ w,
               const float* __restrict__ b, __half* __restrict__ out)
{
    __shared__ float red[8];
    const int row = blockIdx.x;
    const int t   = threadIdx.x;
    const float* xr = in + (size_t)row * CDIM;

    float v0 = xr[t], v1 = xr[t + 256], v2 = xr[t + 512];
    float s = v0 + v1 + v2;
    #pragma unroll
    for (int o = 16; o > 0; o >>= 1) s += __shfl_xor_sync(0xffffffffu, s, o);
    if ((t & 31) == 0) red[t >> 5] = s;
    __syncthreads();
    float mean = (red[0]+red[1]+red[2]+red[3]+red[4]+red[5]+red[6]+red[7]) * (1.f/CDIM);
    __syncthreads();
    float d0 = v0 - mean, d1 = v1 - mean, d2 = v2 - mean;
    float q = d0*d0 + d1*d1 + d2*d2;
    #pragma unroll
    for (int o = 16; o > 0; o >>= 1) q += __shfl_xor_sync(0xffffffffu, q, o);
    if ((t & 31) == 0) red[t >> 5] = q;
    __syncthreads();
    float var = (red[0]+red[1]+red[2]+red[3]+red[4]+red[5]+red[6]+red[7]) * (1.f/CDIM);
    float r = rsqrtf(var + 1e-5f);

    __half* orow = out + (size_t)row * CDIM;
    orow[t]       = __float2half(d0 * r * w[t]       + b[t]);
    orow[t + 256] = __float2half(d1 * r * w[t + 256] + b[t + 256]);
    orow[t + 512] = __float2half(d2 * r * w[t + 512] + b[t + 512]);
}

// ---------------------------------------------------------------------------
// Tensor-core flash attention: block = (qtile of 128, head, batch), 4 warps.
// Q/K/V fp16 from g_qkvH; online softmax with FMA-pipe exp2; out fp16 g_aoH.
// smem: Q 16KB + K 2x8KB + V 2x8KB = 48KB.
// ---------------------------------------------------------------------------
#define ATT_SMEM 49152

__global__ __launch_bounds__(128, 2)
void attn_tc()
{
    extern __shared__ __align__(1024) char smm[];
    const uint32_t sb = smem_u32(smm);
    const uint32_t sQ = sb;

    const int qt = blockIdx.x, hh = blockIdx.y, b = blockIdx.z;
    const int tid = threadIdx.x, lane = tid & 31, wid = tid >> 5;
    const int tok0 = b * SEQ + qt * 128;
    const int wq = wid * 32;

    const __half* Qg = g_qkvH + (size_t)tok0 * C3 + hh * HD;
    const __half* Kg = g_qkvH + (size_t)(b * SEQ) * C3 + CDIM + hh * HD;
    const __half* Vg = Kg + CDIM;

    // load Q tile [128 x 64]
    #pragma unroll
    for (int i = 0; i < 8; i++) {
        int idx = tid + i * 128;
        int row = idx >> 3, c = idx & 7;
        cpa16(sQ + swz8(row, c), Qg + (size_t)row * C3 + c * 8);
    }
    CP_COMMIT();
    // load K/V tile 0 -> buf 0
    #pragma unroll
    for (int i = 0; i < 4; i++) {
        int idx = tid + i * 128;
        int row = idx >> 3, c = idx & 7;
        uint32_t so = swz8(row, c);
        cpa16(sb + 16384 + so, Kg + (size_t)row * C3 + c * 8);
        cpa16(sb + 32768 + so, Vg + (size_t)row * C3 + c * 8);
    }
    CP_COMMIT();
    CP_WAIT0();
    __syncthreads();

    // hoist Q A-fragments (constant over key loop)
    uint32_t qa[2][4][4];
    #pragma unroll
    for (int mi = 0; mi < 2; mi++)
        #pragma unroll
        for (int s = 0; s < 4; s++) {
            int row = wq + mi * 16 + (lane & 15);
            ldmx4(qa[mi][s], sQ + swz8(row, s * 2 + (lane >> 4)));
        }

    float oacc[2][8][4];
    float mrow[2][2], lrow[2][2];
    #pragma unroll
    for (int mi = 0; mi < 2; mi++) {
        mrow[mi][0] = mrow[mi][1] = -1e30f;
        lrow[mi][0] = lrow[mi][1] = 0.f;
        #pragma unroll
        for (int nj = 0; nj < 8; nj++)
            #pragma unroll
            for (int q = 0; q < 4; q++) oacc[mi][nj][q] = 0.f;
    }

    for (int kt = 0; kt < 8; kt++) {
        const uint32_t sK = sb + 16384 + (kt & 1) * 8192;
        const uint32_t sV = sb + 32768 + (kt & 1) * 8192;

        // prefetch next K/V into the other buffer (safe: all warps synced)
        if (kt < 7) {
            const int nt = kt + 1;
            const uint32_t dK = sb + 16384 + (nt & 1) * 8192;
            const uint32_t dV = sb + 32768 + (nt & 1) * 8192;
            const __half* Kn = Kg + (size_t)(nt * 64) * C3;
            const __half* Vn = Vg + (size_t)(nt * 64) * C3;
            #pragma unroll
            for (int i = 0; i < 4; i++) {
                int idx = tid + i * 128;
                int row = idx >> 3, c = idx & 7;
                uint32_t so = swz8(row, c);
                cpa16(dK + so, Kn + (size_t)row * C3 + c * 8);
                cpa16(dV + so, Vn + (size_t)row * C3 + c * 8);
            }
            CP_COMMIT();
        }

        // ---- S = Q K^T ----
        float sacc[2][8][4];
        #pragma unroll
        for (int mi = 0; mi < 2; mi++)
            #pragma unroll
            for (int nj = 0; nj < 8; nj++)
                #pragma unroll
                for (int q = 0; q < 4; q++) sacc[mi][nj][q] = 0.f;

        #pragma unroll
        for (int s = 0; s < 4; s++) {
            uint32_t kb[8][2];
            #pragma unroll
            for (int njp = 0; njp < 4; njp++) {
                uint32_t r[4];
                int row = njp * 16 + (lane & 7) + ((lane >> 4) << 3);
                ldmx4(r, sK + swz8(row, s * 2 + ((lane >> 3) & 1)));
                kb[njp*2][0]   = r[0]; kb[njp*2][1]   = r[1];
                kb[njp*2+1][0] = r[2]; kb[njp*2+1][1] = r[3];
            }
            #pragma unroll
            for (int mi = 0; mi < 2; mi++)
                #pragma unroll
                for (int nj = 0; nj < 8; nj++)
                    mma16816(sacc[mi][nj], qa[mi][s], kb[nj]);
        }

        // ---- online softmax (log2 domain, FMA-pipe exp2) ----
        #pragma unroll
        for (int mi = 0; mi < 2; mi++) {
            #pragma unroll
            for (int hf = 0; hf < 2; hf++) {
                float mx = -1e30f;
                #pragma unroll
                for (int nj = 0; nj < 8; nj++)
                    mx = fmaxf(mx, fmaxf(sacc[mi][nj][hf*2], sacc[mi][nj][hf*2+1]));
                mx *= SCL2E;
                mx = fmaxf(mx, __shfl_xor_sync(0xffffffffu, mx, 1));
                mx = fmaxf(mx, __shfl_xor_sync(0xffffffffu, mx, 2));
                float nm  = fmaxf(mrow[mi][hf], mx);
                float fac = exp2p(mrow[mi][hf] - nm);
                mrow[mi][hf] = nm;
                float rs = 0.f;
                #pragma unroll
                for (int nj = 0; nj < 8; nj++) {
                    float p0 = exp2p(fmaf(sacc[mi][nj][hf*2+0], SCL2E, -nm));
                    float p1 = exp2p(fmaf(sacc[mi][nj][hf*2+1], SCL2E, -nm));
                    sacc[mi][nj][hf*2+0] = p0;
                    sacc[mi][nj][hf*2+1] = p1;
                    rs += p0 + p1;
                }
                rs += __shfl_xor_sync(0xffffffffu, rs, 1);
                rs += __shfl_xor_sync(0xffffffffu, rs, 2);
                lrow[mi][hf] = lrow[mi][hf] * fac + rs;
                #pragma unroll
                for (int nj = 0; nj < 8; nj++) {
                    oacc[mi][nj][hf*2+0] *= fac;
                    oacc[mi][nj][hf*2+1] *= fac;
                }
            }
        }

        // ---- O += P V ----
        #pragma unroll
        for (int j = 0; j < 4; j++) {
            uint32_t pa[2][4];
            #pragma unroll
            for (int mi = 0; mi < 2; mi++) {
                pa[mi][0] = h2u(sacc[mi][2*j][0],   sacc[mi][2*j][1]);
                pa[mi][1] = h2u(sacc[mi][2*j][2],   sacc[mi][2*j][3]);
                pa[mi][2] = h2u(sacc[mi][2*j+1][0], sacc[mi][2*j+1][1]);
                pa[mi][3] = h2u(sacc[mi][2*j+1][2], sacc[mi][2*j+1][3]);
            }
            uint32_t vb[8][2];
            #pragma unroll
            for (int u = 0; u < 4; u++) {
                uint32_t r[4];
                int row = j * 16 + (lane & 15);
                ldmx4t(r, sV + swz8(row, u * 2 + (lane >> 4)));
                vb[u*2][0]   = r[0]; vb[u*2][1]   = r[1];
                vb[u*2+1][0] = r[2]; vb[u*2+1][1] = r[3];
            }
            #pragma unroll
            for (int mi = 0; mi < 2; mi++)
                #pragma unroll
                for (int nj = 0; nj < 8; nj++)
                    mma16816(oacc[mi][nj], pa[mi], vb[nj]);
        }

        if (kt < 7) CP_WAIT0();
        __syncthreads();
    }

    // ---- finalize + store fp16 [B,N,C] ----
    #pragma unroll
    for (int mi = 0; mi < 2; mi++) {
        #pragma unroll
        for (int hf = 0; hf < 2; hf++) {
            float inv = 1.f / lrow[mi][hf];
            int tok = tok0 + wq + mi * 16 + (lane >> 2) + hf * 8;
            __half* dst = g_aoH + (size_t)tok * CDIM + hh * HD + (lane & 3) * 2;
            #pragma unroll
            for (int nj = 0; nj < 8; nj++)
                *(__half2*)(dst + nj * 8) =
                    __floats2half2_rn(oacc[mi][nj][hf*2] * inv, oacc[mi][nj][hf*2+1] * inv);
        }
    }
}

// ---------------------------------------------------------------------------
// Launch
// ---------------------------------------------------------------------------
extern "C" void kernel_launch(void* const* d_in, const int* in_sizes, int n_in,
                              void* d_out, int out_size)
{
    const float* x      = (const float*)d_in[0];
    const float* ln1_w  = (const float*)d_in[1];
    const float* ln1_b  = (const float*)d_in[2];
    const float* qkv_w  = (const float*)d_in[3];
    const float* proj_w = (const float*)d_in[4];
    const float* proj_b = (const float*)d_in[5];
    const float* ln2_w  = (const float*)d_in[6];
    const float* ln2_b  = (const float*)d_in[7];
    const float* fc1_w  = (const float*)d_in[8];
    const float* fc1_b  = (const float*)d_in[9];
    const float* fc2_w  = (const float*)d_in[10];
    const float* fc2_b  = (const float*)d_in[11];
    float* out = (float*)d_out;

    __half *phH, *paoH, *pfc1H, *pqkvH, *pqkvw, *pprojw, *pfc1w, *pfc2w;
    float *px2;
    cudaGetSymbolAddress((void**)&phH,   g_hH);
    cudaGetSymbolAddress((void**)&paoH,  g_aoH);
    cudaGetSymbolAddress((void**)&pfc1H, g_fc1H);
    cudaGetSymbolAddress((void**)&pqkvH, g_qkvH);
    cudaGetSymbolAddress((void**)&px2,   g_x2);
    cudaGetSymbolAddress((void**)&pqkvw, g_qkvw);
    cudaGetSymbolAddress((void**)&pprojw,g_projw);
    cudaGetSymbolAddress((void**)&pfc1w, g_fc1w);
    cudaGetSymbolAddress((void**)&pfc2w, g_fc2w);

    cudaFuncSetAttribute(gemm_hmma<1>, cudaFuncAttributeMaxDynamicSharedMemorySize, GEMM_SMEM);
    cudaFuncSetAttribute(gemm_hmma<2>, cudaFuncAttributeMaxDynamicSharedMemorySize, GEMM_SMEM);
    cudaFuncSetAttribute(gemm_hmma<3>, cudaFuncAttributeMaxDynamicSharedMemorySize, GEMM_SMEM);
    cudaFuncSetAttribute(gemm_hmma<4>, cudaFuncAttributeMaxDynamicSharedMemorySize, GEMM_SMEM);
    cudaFuncSetAttribute(attn_tc,      cudaFuncAttributeMaxDynamicSharedMemorySize, ATT_SMEM);

    // weight conversions
    wconv<<<(C3 * CDIM + 255) / 256, 256>>>(qkv_w,  pqkvw,  C3 * CDIM);
    wconv<<<(CDIM * CDIM + 255) / 256, 256>>>(proj_w, pprojw, CDIM * CDIM);
    wconv<<<(HID * CDIM + 255) / 256, 256>>>(fc1_w,  pfc1w,  HID * CDIM);
    wconv<<<(CDIM * HID + 255) / 256, 256>>>(fc2_w,  pfc2w,  CDIM * HID);

    // 1) LN1 -> fp16
    ln_kernel<<<TOK, 256>>>(x, ln1_w, ln1_b, phH);

    // 2) QKV [16384 x 2304 x 768] -> fp16 g_qkvH
    gemm_hmma<4><<<dim3(C3 / BN, TOK / BM), 256, GEMM_SMEM>>>(
        phH, pqkvw, nullptr, nullptr, nullptr, pqkvH, C3, CDIM);

    // 3) tensor-core flash attention -> fp16 g_aoH
    attn_tc<<<dim3(SEQ / 128, NHEAD, BATCH), 128, ATT_SMEM>>>();

    // 4) x = 2*(attn @ proj_w^T + proj_b) -> fp32 g_x2
    gemm_hmma<1><<<dim3(CDIM / BN, TOK / BM), 256, GEMM_SMEM>>>(
        paoH, pprojw, proj_b, nullptr, px2, nullptr, CDIM, CDIM);

    // 5) LN2 -> fp16
    ln_kernel<<<TOK, 256>>>(px2, ln2_w, ln2_b, phH);

    // 6) FC1 + GELU -> fp16 g_fc1H  [16384 x 3072 x 768]
    gemm_hmma<2><<<dim3(HID / BN, TOK / BM), 256, GEMM_SMEM>>>(
        phH, pfc1w, fc1_b, nullptr, nullptr, pfc1H, HID, CDIM);

    // 7) out = fc1g @ fc2_w^T + fc2_b + x  [16384 x 768 x 3072]
    gemm_hmma<3><<<dim3(CDIM / BN, TOK / BM), 256, GEMM_SMEM>>>(
        pfc1H, pfc2w, fc2_b, px2, out, nullptr, CDIM, HID);
}